// round 14
// baseline (speedup 1.0000x reference)
#include <cuda_runtime.h>
#include <math.h>

#define BB 8
#define NN 8192
#define HH 32
#define WW 32
#define DD 256
#define HW (HH * WW)                 // 1024
#define ZQ_SIZE (BB * DD * HH * WW)  // 2097152
#define NPOS (BB * HH * WW)          // 8192
#define NGRP 256                     // one CTA per (b,h)
#define KLW 5e-4f
#define LOG_N 9.010913347279288f     // log(8192)

__device__ float        g_kl_partial[NGRP];
__device__ unsigned int g_arrive = 0;          // self-resetting; replay-safe

__global__ void __launch_bounds__(512, 2)
gumbel_fused_kernel(const float* __restrict__ z,
                    const float* __restrict__ Wt,
                    const float* __restrict__ g,
                    float* __restrict__ out)
{
    const int bh  = blockIdx.x;      // 0..255 = (b,h)
    const int b   = bh >> 5;
    const int h   = bh & 31;
    const int tid = threadIdx.x;     // 0..511
    const int grp = tid & 7;         // w-quad: w = grp*4..+3 (warp covers all 32 w)
    const int np  = tid >> 3;        // n-partition 0..63

    // smem: stats 32KB (phases 1-2) overlaid by 16.5KB gather rows (phase 3)
    __shared__ __align__(16) unsigned char s_buf[64 * 32 * 4 * 4];  // 32KB
    float (*s_m1)[32] = (float (*)[32])(s_buf);             // [64][32] 8KB
    int   (*s_a1)[32] = (int   (*)[32])(s_buf + 8192);
    float (*s_S )[32] = (float (*)[32])(s_buf + 16384);
    float (*s_T )[32] = (float (*)[32])(s_buf + 24576);
    float (*s_rows)[129] = (float (*)[129])(s_buf);         // [32][129] 16.5KB
    __shared__ int   s_ind[32];
    __shared__ bool  s_fin;

    // thread rows: n = np + i*64, i = 0..127; warp-LDG = 4 full 128B lines
    const long long base = (long long)(b * NN + np) * HW + h * WW + grp * 4;
    const float4* zp = (const float4*)(z + base);
    const float4* gp = (const float4*)(g + base);
    const int strideV = 64 * HW / 4;          // 16384 float4 per iteration

    float m1x=-INFINITY, m1y=-INFINITY, m1z=-INFINITY, m1w=-INFINITY;
    int   a1x=0, a1y=0, a1z=0, a1w=0;
    float Sx=0.f, Sy=0.f, Sz=0.f, Sw=0.f;
    float Tx=0.f, Ty=0.f, Tz=0.f, Tw=0.f;

    #pragma unroll 4
    for (int i = 0; i < 128; ++i, zp += strideV, gp += strideV) {
        const int n = np + i * 64;
        const float4 zv = __ldcs(zp);        // streaming: evict-first
        const float4 gv = __ldcs(gp);

        // argmax of z+g (strict > keeps first index, like jnp.argmax)
        float lg;
        lg = zv.x + gv.x; if (lg > m1x) { m1x = lg; a1x = n; }
        lg = zv.y + gv.y; if (lg > m1y) { m1y = lg; a1y = n; }
        lg = zv.z + gv.z; if (lg > m1z) { m1z = lg; a1z = n; }
        lg = zv.w + gv.w; if (lg > m1w) { m1w = lg; a1w = n; }

        // shift-free softmax stats: z ~ N(0,1) -> exp safe in fp32
        float e;
        e = __expf(zv.x); Sx += e; Tx = fmaf(e, zv.x, Tx);
        e = __expf(zv.y); Sy += e; Ty = fmaf(e, zv.y, Ty);
        e = __expf(zv.z); Sz += e; Tz = fmaf(e, zv.z, Tz);
        e = __expf(zv.w); Sw += e; Tw = fmaf(e, zv.w, Tw);
    }

    const int w0 = grp * 4;
    s_m1[np][w0+0]=m1x; s_m1[np][w0+1]=m1y; s_m1[np][w0+2]=m1z; s_m1[np][w0+3]=m1w;
    s_a1[np][w0+0]=a1x; s_a1[np][w0+1]=a1y; s_a1[np][w0+2]=a1z; s_a1[np][w0+3]=a1w;
    s_S [np][w0+0]=Sx;  s_S [np][w0+1]=Sy;  s_S [np][w0+2]=Sz;  s_S [np][w0+3]=Sw;
    s_T [np][w0+0]=Tx;  s_T [np][w0+1]=Ty;  s_T [np][w0+2]=Tz;  s_T [np][w0+3]=Tw;
    __syncthreads();

    // warp 0: lane w combines the 64 n-partitions for its (b,h,w)
    if (tid < 32) {
        const int w = tid;
        float M1 = s_m1[0][w]; int A1 = s_a1[0][w];
        float S = s_S[0][w];  float T = s_T[0][w];
        #pragma unroll 8
        for (int i = 1; i < 64; ++i) {
            const float v = s_m1[i][w]; const int a = s_a1[i][w];
            if (v > M1 || (v == M1 && a < A1)) { M1 = v; A1 = a; }
            S += s_S[i][w];
            T += s_T[i][w];
        }
        float kl = T / S - __logf(S) + LOG_N;

        s_ind[w] = A1;
        out[ZQ_SIZE + 1 + bh * 32 + w] = (float)A1;

        #pragma unroll
        for (int off = 16; off; off >>= 1)
            kl += __shfl_xor_sync(0xffffffffu, kl, off);
        if (w == 0) g_kl_partial[bh] = kl;
    }
    __syncthreads();                 // stats scratch free -> reuse as s_rows

    // ---- z_q gather + transposed write, staged in two d-halves ----
    {
        const int lane = tid & 31;
        const int wid  = tid >> 5;   // 16 warps
        const long long obase = (long long)(b * DD) * HW + h * WW + lane;
        #pragma unroll
        for (int halfd = 0; halfd < 2; ++halfd) {
            const int d0 = halfd * 128;
            // 16 warps x 2 rows each; each warp reads 128 floats/row coalesced
            #pragma unroll
            for (int r = wid; r < 32; r += 16) {
                const int row = s_ind[r];
                #pragma unroll
                for (int c = 0; c < 4; ++c)
                    s_rows[r][c * 32 + lane] =
                        __ldg(Wt + row * DD + d0 + c * 32 + lane);
            }
            __syncthreads();
            // write: lane = w (128B stores); 16 warps x 8 d each
            #pragma unroll 8
            for (int k = 0; k < 8; ++k) {
                const int dl = wid * 8 + k;          // 0..127 d-local
                __stcs(&out[obase + (long long)(d0 + dl) * HW],
                       s_rows[lane][dl]);            // streaming store
            }
            __syncthreads();
        }
    }

    // ---- last-CTA finalize: reduce 256 KL partials ----
    if (tid == 0) {
        __threadfence();
        const unsigned old = atomicAdd(&g_arrive, 1u);
        s_fin = (old == NGRP - 1);
    }
    __syncthreads();
    if (s_fin) {
        __threadfence();
        if (tid < 256) {
            float v = g_kl_partial[tid];
            #pragma unroll
            for (int off = 16; off; off >>= 1)
                v += __shfl_xor_sync(0xffffffffu, v, off);
            __shared__ float s_red[8];
            if ((tid & 31) == 0) s_red[tid >> 5] = v;
            __syncwarp();
            if (tid == 0) {
                float x = 0.f;
                #pragma unroll
                for (int j = 0; j < 8; ++j) x += s_red[j];
                out[ZQ_SIZE] = KLW * (x / (float)NPOS);
                g_arrive = 0;                // reset for next replay
            }
        }
    }
}

extern "C" void kernel_launch(void* const* d_in, const int* in_sizes, int n_in,
                              void* d_out, int out_size)
{
    const float* z  = (const float*)d_in[0];
    const float* Wt = (const float*)d_in[1];
    const float* g  = (const float*)d_in[2];
    float* out = (float*)d_out;

    gumbel_fused_kernel<<<NGRP, 512>>>(z, Wt, g, out);
}

// round 16
// speedup vs baseline: 1.0239x; 1.0239x over previous
#include <cuda_runtime.h>
#include <math.h>

#define BB 8
#define NN 8192
#define HH 32
#define WW 32
#define DD 256
#define HW (HH * WW)                 // 1024
#define ZQ_SIZE (BB * DD * HH * WW)  // 2097152
#define NPOS (BB * HH * WW)          // 8192
#define NGRP 256                     // one CTA per (b,h)
#define KLW 5e-4f
#define LOG_N 9.010913347279288f     // log(8192)

__device__ float        g_kl_partial[NGRP];
__device__ unsigned int g_arrive = 0;          // self-resetting; replay-safe

__global__ void __launch_bounds__(512, 2)
gumbel_fused_kernel(const float* __restrict__ z,
                    const float* __restrict__ Wt,
                    const float* __restrict__ g,
                    float* __restrict__ out)
{
    const int bh  = blockIdx.x;      // 0..255 = (b,h)
    const int b   = bh >> 5;
    const int h   = bh & 31;
    const int tid = threadIdx.x;     // 0..511
    const int grp = tid & 7;         // w-quad: w = grp*4..+3 (warp covers all 32 w)
    const int np  = tid >> 3;        // n-partition 0..63

    // smem: stats 32KB (phases 1-2) overlaid by 16.5KB gather rows (phase 3)
    __shared__ __align__(16) unsigned char s_buf[64 * 32 * 4 * 4];  // 32KB
    float (*s_m1)[32] = (float (*)[32])(s_buf);             // [64][32] 8KB
    int   (*s_a1)[32] = (int   (*)[32])(s_buf + 8192);
    float (*s_S )[32] = (float (*)[32])(s_buf + 16384);
    float (*s_T )[32] = (float (*)[32])(s_buf + 24576);
    float (*s_rows)[129] = (float (*)[129])(s_buf);         // [32][129] 16.5KB
    __shared__ int   s_ind[32];
    __shared__ float s_red[16];
    __shared__ bool  s_fin;

    // thread rows: n = np + i*64, i = 0..127; warp-LDG = 4 full 128B lines
    const long long base = (long long)(b * NN + np) * HW + h * WW + grp * 4;
    const float4* zp = (const float4*)(z + base);
    const float4* gp = (const float4*)(g + base);
    const int strideV = 64 * HW / 4;          // 16384 float4 per iteration

    float m1x=-INFINITY, m1y=-INFINITY, m1z=-INFINITY, m1w=-INFINITY;
    int   a1x=0, a1y=0, a1z=0, a1w=0;
    float Sx=0.f, Sy=0.f, Sz=0.f, Sw=0.f;
    float Tx=0.f, Ty=0.f, Tz=0.f, Tw=0.f;

    #pragma unroll 4
    for (int i = 0; i < 128; ++i, zp += strideV, gp += strideV) {
        const int n = np + i * 64;
        const float4 zv = __ldcs(zp);        // streaming: evict-first
        const float4 gv = __ldcs(gp);

        // argmax of z+g (strict > keeps first index, like jnp.argmax)
        float lg;
        lg = zv.x + gv.x; if (lg > m1x) { m1x = lg; a1x = n; }
        lg = zv.y + gv.y; if (lg > m1y) { m1y = lg; a1y = n; }
        lg = zv.z + gv.z; if (lg > m1z) { m1z = lg; a1z = n; }
        lg = zv.w + gv.w; if (lg > m1w) { m1w = lg; a1w = n; }

        // shift-free softmax stats: z ~ N(0,1) -> exp safe in fp32
        float e;
        e = __expf(zv.x); Sx += e; Tx = fmaf(e, zv.x, Tx);
        e = __expf(zv.y); Sy += e; Ty = fmaf(e, zv.y, Ty);
        e = __expf(zv.z); Sz += e; Tz = fmaf(e, zv.z, Tz);
        e = __expf(zv.w); Sw += e; Tw = fmaf(e, zv.w, Tw);
    }

    const int w0 = grp * 4;
    s_m1[np][w0+0]=m1x; s_m1[np][w0+1]=m1y; s_m1[np][w0+2]=m1z; s_m1[np][w0+3]=m1w;
    s_a1[np][w0+0]=a1x; s_a1[np][w0+1]=a1y; s_a1[np][w0+2]=a1z; s_a1[np][w0+3]=a1w;
    s_S [np][w0+0]=Sx;  s_S [np][w0+1]=Sy;  s_S [np][w0+2]=Sz;  s_S [np][w0+3]=Sw;
    s_T [np][w0+0]=Tx;  s_T [np][w0+1]=Ty;  s_T [np][w0+2]=Tz;  s_T [np][w0+3]=Tw;
    __syncthreads();

    // warp 0: lane w combines the 64 n-partitions for its (b,h,w)
    if (tid < 32) {
        const int w = tid;
        float M1 = s_m1[0][w]; int A1 = s_a1[0][w];
        float S = s_S[0][w];  float T = s_T[0][w];
        #pragma unroll 8
        for (int i = 1; i < 64; ++i) {
            const float v = s_m1[i][w]; const int a = s_a1[i][w];
            if (v > M1 || (v == M1 && a < A1)) { M1 = v; A1 = a; }
            S += s_S[i][w];
            T += s_T[i][w];
        }
        float kl = T / S - __logf(S) + LOG_N;

        s_ind[w] = A1;
        out[ZQ_SIZE + 1 + bh * 32 + w] = (float)A1;

        #pragma unroll
        for (int off = 16; off; off >>= 1)
            kl += __shfl_xor_sync(0xffffffffu, kl, off);
        if (w == 0) g_kl_partial[bh] = kl;
    }
    __syncthreads();                 // stats scratch free -> reuse as s_rows

    // ---- z_q gather + transposed write, staged in two d-halves ----
    {
        const int lane = tid & 31;
        const int wid  = tid >> 5;   // 16 warps
        const long long obase = (long long)(b * DD) * HW + h * WW + lane;
        #pragma unroll
        for (int halfd = 0; halfd < 2; ++halfd) {
            const int d0 = halfd * 128;
            // 16 warps x 2 rows each; each warp reads 128 floats/row coalesced
            #pragma unroll
            for (int r = wid; r < 32; r += 16) {
                const int row = s_ind[r];
                #pragma unroll
                for (int c = 0; c < 4; ++c)
                    s_rows[r][c * 32 + lane] =
                        __ldg(Wt + row * DD + d0 + c * 32 + lane);
            }
            __syncthreads();
            // write: lane = w (128B stores); 16 warps x 8 d each
            #pragma unroll 8
            for (int k = 0; k < 8; ++k) {
                const int dl = wid * 8 + k;          // 0..127 d-local
                __stcs(&out[obase + (long long)(d0 + dl) * HW],
                       s_rows[lane][dl]);            // streaming store
            }
            __syncthreads();
        }
    }

    // ---- last-CTA finalize: reduce 256 KL partials (race-free handoff) ----
    if (tid == 0) {
        __threadfence();
        const unsigned old = atomicAdd(&g_arrive, 1u);
        s_fin = (old == NGRP - 1);
    }
    __syncthreads();                 // broadcast s_fin (uniform across CTA)
    if (s_fin) {
        __threadfence();             // acquire: peer g_kl_partial writes visible
        float v = (tid < 256) ? g_kl_partial[tid] : 0.f;
        #pragma unroll
        for (int off = 16; off; off >>= 1)
            v += __shfl_xor_sync(0xffffffffu, v, off);
        if ((tid & 31) == 0) s_red[tid >> 5] = v;    // 16 warps -> 16 slots
        __syncthreads();             // REAL inter-warp sync (uniform branch)
        if (tid == 0) {
            float x = 0.f;
            #pragma unroll
            for (int j = 0; j < 16; ++j) x += s_red[j];
            out[ZQ_SIZE] = KLW * (x / (float)NPOS);
            g_arrive = 0;            // reset for next graph replay
        }
    }
}

extern "C" void kernel_launch(void* const* d_in, const int* in_sizes, int n_in,
                              void* d_out, int out_size)
{
    const float* z  = (const float*)d_in[0];
    const float* Wt = (const float*)d_in[1];
    const float* g  = (const float*)d_in[2];
    float* out = (float*)d_out;

    gumbel_fused_kernel<<<NGRP, 512>>>(z, Wt, g, out);
}